// round 3
// baseline (speedup 1.0000x reference)
#include <cuda_runtime.h>
#include <cstdint>

// Problem-fixed maxima (N=100000, E=3200000 per reference setup_inputs).
#define MAXN 100000
#define MAXE 3200000

// Scratch (allocation-free contract: __device__ globals).
__device__ __align__(16) float g_deg[MAXN];          // degree, then overwritten with dinv
__device__ __align__(16) float g_t1[MAXN * 32];      // x @ W1
__device__ __align__(16) float g_acc1[MAXN * 32];    // layer-1 aggregation accumulator
__device__ __align__(16) float g_t2[MAXN * 3];       // h @ W2

__device__ __forceinline__ void red_add_v4(float* addr, float a, float b, float c, float d) {
    asm volatile("red.global.add.v4.f32 [%0], {%1, %2, %3, %4};"
                 :: "l"(addr), "f"(a), "f"(b), "f"(c), "f"(d) : "memory");
}

__device__ __forceinline__ void red_add_f32(float* addr, float a) {
    asm volatile("red.global.add.f32 [%0], %1;" :: "l"(addr), "f"(a) : "memory");
}

// 1) deg[i] = 1.0 (self-loop)
__global__ void k_init_deg(int n) {
    int i = blockIdx.x * blockDim.x + threadIdx.x;
    if (i < n) g_deg[i] = 1.0f;
}

// 2) in-degree histogram (edge_index is int32: JAX x64 disabled downcasts int64)
__global__ void k_degree(const int* __restrict__ edge_index, int E) {
    int e = blockIdx.x * blockDim.x + threadIdx.x;
    if (e >= E) return;
    int d = edge_index[E + e];
    red_add_f32(&g_deg[d], 1.0f);
}

// 3) dinv = rsqrt(deg); t1 = x @ W1; acc1 = t1 * dinv^2 (self-loop term folded in)
__global__ void k_transform1(const float* __restrict__ x, const float* __restrict__ W1, int n) {
    __shared__ float sW[96];  // W1 is [3, 32] row-major
    if (threadIdx.x < 96) sW[threadIdx.x] = W1[threadIdx.x];
    __syncthreads();
    int i = blockIdx.x * blockDim.x + threadIdx.x;
    if (i >= n) return;
    float di = rsqrtf(g_deg[i]);
    g_deg[i] = di;  // in-place: each thread touches only its own slot
    float x0 = x[i * 3 + 0], x1 = x[i * 3 + 1], x2 = x[i * 3 + 2];
    float sl = di * di;
    float4* t1 = reinterpret_cast<float4*>(&g_t1[i * 32]);
    float4* a1 = reinterpret_cast<float4*>(&g_acc1[i * 32]);
#pragma unroll
    for (int j = 0; j < 32; j += 4) {
        float4 t;
        t.x = x0 * sW[j + 0] + x1 * sW[32 + j + 0] + x2 * sW[64 + j + 0];
        t.y = x0 * sW[j + 1] + x1 * sW[32 + j + 1] + x2 * sW[64 + j + 1];
        t.z = x0 * sW[j + 2] + x1 * sW[32 + j + 2] + x2 * sW[64 + j + 2];
        t.w = x0 * sW[j + 3] + x1 * sW[32 + j + 3] + x2 * sW[64 + j + 3];
        t1[j >> 2] = t;
        float4 a;
        a.x = t.x * sl; a.y = t.y * sl; a.z = t.z * sl; a.w = t.w * sl;
        a1[j >> 2] = a;
    }
}

// 4) layer-1 scatter: 8 lanes per edge, each lane moves one float4 with red.v4
__global__ void k_scatter1(const int* __restrict__ edge_index, int E) {
    int tid = blockIdx.x * blockDim.x + threadIdx.x;
    int e = tid >> 3;
    int q = tid & 7;
    if (e >= E) return;
    int s = edge_index[e];
    int d = edge_index[E + e];
    float w = g_deg[s] * g_deg[d];  // dinv[src] * dinv[dst]
    float4 v = reinterpret_cast<const float4*>(g_t1)[s * 8 + q];
    float* dst = &g_acc1[d * 32 + q * 4];
    red_add_v4(dst, v.x * w, v.y * w, v.z * w, v.w * w);
}

// 5) h = relu(acc1 + b1); t2 = h @ W2; out = t2 * dinv^2 + b2 (self-loop + bias folded)
__global__ void k_transform2(const float* __restrict__ b1, const float* __restrict__ W2,
                             const float* __restrict__ b2, float* __restrict__ out, int n) {
    __shared__ float sW[96];  // W2 is [32, 3] row-major
    __shared__ float sb1[32];
    __shared__ float sb2[3];
    if (threadIdx.x < 96) sW[threadIdx.x] = W2[threadIdx.x];
    if (threadIdx.x < 32) sb1[threadIdx.x] = b1[threadIdx.x];
    if (threadIdx.x < 3) sb2[threadIdx.x] = b2[threadIdx.x];
    __syncthreads();
    int i = blockIdx.x * blockDim.x + threadIdx.x;
    if (i >= n) return;
    float di = g_deg[i];
    float c0 = 0.f, c1 = 0.f, c2 = 0.f;
    const float4* a1 = reinterpret_cast<const float4*>(&g_acc1[i * 32]);
#pragma unroll
    for (int jj = 0; jj < 8; jj++) {
        float4 a = a1[jj];
        float hv[4] = {a.x, a.y, a.z, a.w};
#pragma unroll
        for (int k = 0; k < 4; k++) {
            int j = jj * 4 + k;
            float h = fmaxf(hv[k] + sb1[j], 0.f);
            c0 += h * sW[j * 3 + 0];
            c1 += h * sW[j * 3 + 1];
            c2 += h * sW[j * 3 + 2];
        }
    }
    g_t2[i * 3 + 0] = c0;
    g_t2[i * 3 + 1] = c1;
    g_t2[i * 3 + 2] = c2;
    float sl = di * di;
    out[i * 3 + 0] = c0 * sl + sb2[0];
    out[i * 3 + 1] = c1 * sl + sb2[1];
    out[i * 3 + 2] = c2 * sl + sb2[2];
}

// 6) layer-2 scatter: 1 thread per edge, 3 scalar reds into d_out
__global__ void k_scatter2(const int* __restrict__ edge_index, float* __restrict__ out, int E) {
    int e = blockIdx.x * blockDim.x + threadIdx.x;
    if (e >= E) return;
    int s = edge_index[e];
    int d = edge_index[E + e];
    float w = g_deg[s] * g_deg[d];
    const float* tp = &g_t2[s * 3];
    float* op = &out[d * 3];
    red_add_f32(&op[0], tp[0] * w);
    red_add_f32(&op[1], tp[1] * w);
    red_add_f32(&op[2], tp[2] * w);
}

extern "C" void kernel_launch(void* const* d_in, const int* in_sizes, int n_in,
                              void* d_out, int out_size) {
    const float* x = (const float*)d_in[0];
    const int* edge_index = (const int*)d_in[1];  // int32 (JAX x64 disabled)
    const float* W1 = (const float*)d_in[2];
    const float* b1 = (const float*)d_in[3];
    const float* W2 = (const float*)d_in[4];
    const float* b2 = (const float*)d_in[5];
    float* out = (float*)d_out;

    int n = in_sizes[0] / 3;
    int E = in_sizes[1] / 2;

    const int B = 256;
    k_init_deg<<<(n + B - 1) / B, B>>>(n);
    k_degree<<<(E + B - 1) / B, B>>>(edge_index, E);
    k_transform1<<<(n + B - 1) / B, B>>>(x, W1, n);
    {
        long long threads = (long long)E * 8;
        k_scatter1<<<(unsigned)((threads + B - 1) / B), B>>>(edge_index, E);
    }
    k_transform2<<<(n + B - 1) / B, B>>>(b1, W2, b2, out, n);
    k_scatter2<<<(E + B - 1) / B, B>>>(edge_index, out, E);
}

// round 7
// speedup vs baseline: 1.1592x; 1.1592x over previous
#include <cuda_runtime.h>
#include <cstdint>

// Problem-fixed maxima (N=100000, E=3200000 per reference setup_inputs).
#define MAXN 100000
#define MAXE 3200000

// Scratch (allocation-free contract: __device__ globals).
__device__ __align__(16) float g_deg[MAXN];           // degree, then overwritten with dinv
__device__ __align__(16) float g_t1[MAXN * 32];       // x @ W1
__device__ __align__(16) float g_acc1[MAXN * 32];     // layer-1 aggregation accumulator
__device__ __align__(16) float g_t2[MAXN * 4];        // h @ W2 (padded to 4)
__device__ __align__(16) float g_acc2[MAXN * 4];      // layer-2 accumulator (padded to 4)

__device__ __forceinline__ void red_add_v4(float* addr, float a, float b, float c, float d) {
    asm volatile("red.global.add.v4.f32 [%0], {%1, %2, %3, %4};"
                 :: "l"(addr), "f"(a), "f"(b), "f"(c), "f"(d) : "memory");
}

__device__ __forceinline__ void red_add_f32(float* addr, float a) {
    asm volatile("red.global.add.f32 [%0], %1;" :: "l"(addr), "f"(a) : "memory");
}

// 1) deg[i] = 1.0 (self-loop)
__global__ void k_init_deg(int n) {
    int i = blockIdx.x * blockDim.x + threadIdx.x;
    if (i < n) g_deg[i] = 1.0f;
}

// 2) in-degree histogram, 4 edges per thread via int4 loads
__global__ void k_degree4(const int* __restrict__ edge_index, int E) {
    int i = blockIdx.x * blockDim.x + threadIdx.x;
    int e0 = i * 4;
    if (e0 >= E) return;
    const int* dstp = edge_index + E;
    if (e0 + 3 < E) {
        int4 d4 = *reinterpret_cast<const int4*>(dstp + e0);
        red_add_f32(&g_deg[d4.x], 1.0f);
        red_add_f32(&g_deg[d4.y], 1.0f);
        red_add_f32(&g_deg[d4.z], 1.0f);
        red_add_f32(&g_deg[d4.w], 1.0f);
    } else {
        for (int e = e0; e < E; e++) red_add_f32(&g_deg[dstp[e]], 1.0f);
    }
}

// 3) dinv = rsqrt(deg); t1 = x @ W1; acc1 = t1 * dinv^2 (self-loop term folded in)
__global__ void k_transform1(const float* __restrict__ x, const float* __restrict__ W1, int n) {
    __shared__ float sW[96];  // W1 is [3, 32] row-major
    if (threadIdx.x < 96) sW[threadIdx.x] = W1[threadIdx.x];
    __syncthreads();
    int i = blockIdx.x * blockDim.x + threadIdx.x;
    if (i >= n) return;
    float di = rsqrtf(g_deg[i]);
    g_deg[i] = di;  // in-place: each thread touches only its own slot
    float x0 = x[i * 3 + 0], x1 = x[i * 3 + 1], x2 = x[i * 3 + 2];
    float sl = di * di;
    float4* t1 = reinterpret_cast<float4*>(&g_t1[i * 32]);
    float4* a1 = reinterpret_cast<float4*>(&g_acc1[i * 32]);
#pragma unroll
    for (int j = 0; j < 32; j += 4) {
        float4 t;
        t.x = x0 * sW[j + 0] + x1 * sW[32 + j + 0] + x2 * sW[64 + j + 0];
        t.y = x0 * sW[j + 1] + x1 * sW[32 + j + 1] + x2 * sW[64 + j + 1];
        t.z = x0 * sW[j + 2] + x1 * sW[32 + j + 2] + x2 * sW[64 + j + 2];
        t.w = x0 * sW[j + 3] + x1 * sW[32 + j + 3] + x2 * sW[64 + j + 3];
        t1[j >> 2] = t;
        float4 a;
        a.x = t.x * sl; a.y = t.y * sl; a.z = t.z * sl; a.w = t.w * sl;
        a1[j >> 2] = a;
    }
}

// 4) layer-1 scatter: 8 lanes per edge; leader lane loads indices/weights once,
//    broadcast via shuffle. Each lane moves one float4 with red.v4.
__global__ void k_scatter1(const int* __restrict__ edge_index, int E) {
    int tid = blockIdx.x * blockDim.x + threadIdx.x;
    int e = tid >> 3;
    int q = tid & 7;
    bool valid = (e < E);
    int esafe = valid ? e : 0;
    int lane = threadIdx.x & 31;
    int leader = lane & ~7;

    int s = 0, d = 0;
    float w = 0.f;
    if (q == 0) {
        s = edge_index[esafe];
        d = edge_index[E + esafe];
        w = g_deg[s] * g_deg[d];  // dinv[src] * dinv[dst]
    }
    s = __shfl_sync(0xffffffffu, s, leader);
    d = __shfl_sync(0xffffffffu, d, leader);
    w = __shfl_sync(0xffffffffu, w, leader);

    if (!valid) return;
    float4 v = reinterpret_cast<const float4*>(g_t1)[s * 8 + q];
    float* dst = &g_acc1[d * 32 + q * 4];
    red_add_v4(dst, v.x * w, v.y * w, v.z * w, v.w * w);
}

// 5) h = relu(acc1 + b1); t2 = h @ W2 (padded); acc2 = t2 * dinv^2 (self-loop seeded)
__global__ void k_transform2(const float* __restrict__ b1, const float* __restrict__ W2, int n) {
    __shared__ float sW[96];  // W2 is [32, 3] row-major
    __shared__ float sb1[32];
    if (threadIdx.x < 96) sW[threadIdx.x] = W2[threadIdx.x];
    if (threadIdx.x < 32) sb1[threadIdx.x] = b1[threadIdx.x];
    __syncthreads();
    int i = blockIdx.x * blockDim.x + threadIdx.x;
    if (i >= n) return;
    float di = g_deg[i];
    float c0 = 0.f, c1 = 0.f, c2 = 0.f;
    const float4* a1 = reinterpret_cast<const float4*>(&g_acc1[i * 32]);
#pragma unroll
    for (int jj = 0; jj < 8; jj++) {
        float4 a = a1[jj];
        float hv[4] = {a.x, a.y, a.z, a.w};
#pragma unroll
        for (int k = 0; k < 4; k++) {
            int j = jj * 4 + k;
            float h = fmaxf(hv[k] + sb1[j], 0.f);
            c0 += h * sW[j * 3 + 0];
            c1 += h * sW[j * 3 + 1];
            c2 += h * sW[j * 3 + 2];
        }
    }
    float4 t = make_float4(c0, c1, c2, 0.f);
    reinterpret_cast<float4*>(g_t2)[i] = t;
    float sl = di * di;
    reinterpret_cast<float4*>(g_acc2)[i] = make_float4(c0 * sl, c1 * sl, c2 * sl, 0.f);
}

// 6) layer-2 scatter: 1 thread per edge, one LDG.128 + one red.v4
__global__ void k_scatter2(const int* __restrict__ edge_index, int E) {
    int e = blockIdx.x * blockDim.x + threadIdx.x;
    if (e >= E) return;
    int s = edge_index[e];
    int d = edge_index[E + e];
    float w = g_deg[s] * g_deg[d];
    float4 t = reinterpret_cast<const float4*>(g_t2)[s];
    red_add_v4(&g_acc2[d * 4], t.x * w, t.y * w, t.z * w, 0.f);
}

// 7) out[i, :] = acc2[i, 0:3] + b2
__global__ void k_out(const float* __restrict__ b2, float* __restrict__ out, int n) {
    int i = blockIdx.x * blockDim.x + threadIdx.x;
    if (i >= n) return;
    float4 a = reinterpret_cast<const float4*>(g_acc2)[i];
    out[i * 3 + 0] = a.x + b2[0];
    out[i * 3 + 1] = a.y + b2[1];
    out[i * 3 + 2] = a.z + b2[2];
}

extern "C" void kernel_launch(void* const* d_in, const int* in_sizes, int n_in,
                              void* d_out, int out_size) {
    const float* x = (const float*)d_in[0];
    const int* edge_index = (const int*)d_in[1];  // int32 (JAX x64 disabled)
    const float* W1 = (const float*)d_in[2];
    const float* b1 = (const float*)d_in[3];
    const float* W2 = (const float*)d_in[4];
    const float* b2 = (const float*)d_in[5];
    float* out = (float*)d_out;

    int n = in_sizes[0] / 3;
    int E = in_sizes[1] / 2;

    const int B = 256;
    k_init_deg<<<(n + B - 1) / B, B>>>(n);
    {
        int t = (E + 3) / 4;
        k_degree4<<<(t + B - 1) / B, B>>>(edge_index, E);
    }
    k_transform1<<<(n + B - 1) / B, B>>>(x, W1, n);
    {
        long long threads = (long long)E * 8;
        k_scatter1<<<(unsigned)((threads + B - 1) / B), B>>>(edge_index, E);
    }
    k_transform2<<<(n + B - 1) / B, B>>>(b1, W2, n);
    k_scatter2<<<(E + B - 1) / B, B>>>(edge_index, E);
    k_out<<<(n + B - 1) / B, B>>>(b2, out, n);
}

// round 8
// speedup vs baseline: 1.7791x; 1.5349x over previous
#include <cuda_runtime.h>
#include <cstdint>

// Problem-fixed maxima (N=100000, E=3200000 per reference setup_inputs).
#define MAXN 100000
#define MAXE 3200000

// Scratch (allocation-free contract: __device__ globals).
__device__ __align__(16) float g_deg[MAXN];        // degree, then overwritten with dinv
__device__ __align__(16) float g_x4[MAXN * 4];     // x padded to float4
__device__ __align__(16) float g_accx[MAXN * 4];   // layer-1 aggregation of RAW x (pre-transform)
__device__ __align__(16) float g_t2[MAXN * 4];     // h @ W2 (padded to 4)
__device__ __align__(16) float g_acc2[MAXN * 4];   // layer-2 accumulator (padded to 4)

__device__ __forceinline__ void red_add_v4(float* addr, float a, float b, float c, float d) {
    asm volatile("red.global.add.v4.f32 [%0], {%1, %2, %3, %4};"
                 :: "l"(addr), "f"(a), "f"(b), "f"(c), "f"(d) : "memory");
}

__device__ __forceinline__ void red_add_f32(float* addr, float a) {
    asm volatile("red.global.add.f32 [%0], %1;" :: "l"(addr), "f"(a) : "memory");
}

// 1) deg[i] = 1.0 (self-loop)
__global__ void k_init_deg(int n) {
    int i = blockIdx.x * blockDim.x + threadIdx.x;
    if (i < n) g_deg[i] = 1.0f;
}

// 2) in-degree histogram, 4 edges per thread via int4 loads
__global__ void k_degree4(const int* __restrict__ edge_index, int E) {
    int i = blockIdx.x * blockDim.x + threadIdx.x;
    int e0 = i * 4;
    if (e0 >= E) return;
    const int* dstp = edge_index + E;
    if (e0 + 3 < E) {
        int4 d4 = *reinterpret_cast<const int4*>(dstp + e0);
        red_add_f32(&g_deg[d4.x], 1.0f);
        red_add_f32(&g_deg[d4.y], 1.0f);
        red_add_f32(&g_deg[d4.z], 1.0f);
        red_add_f32(&g_deg[d4.w], 1.0f);
    } else {
        for (int e = e0; e < E; e++) red_add_f32(&g_deg[dstp[e]], 1.0f);
    }
}

// 3) dinv = rsqrt(deg); pad x to float4; seed layer-1 accumulator with self-loop term
__global__ void k_prep(const float* __restrict__ x, int n) {
    int i = blockIdx.x * blockDim.x + threadIdx.x;
    if (i >= n) return;
    float di = rsqrtf(g_deg[i]);
    g_deg[i] = di;  // in-place: each thread touches only its own slot
    float x0 = x[i * 3 + 0], x1 = x[i * 3 + 1], x2 = x[i * 3 + 2];
    reinterpret_cast<float4*>(g_x4)[i] = make_float4(x0, x1, x2, 0.f);
    float sl = di * di;
    reinterpret_cast<float4*>(g_accx)[i] = make_float4(x0 * sl, x1 * sl, x2 * sl, 0.f);
}

// 4) layer-1 scatter on RAW x (3-wide): 1 thread/edge, one LDG.128 + one red.v4.
//    Valid because aggregation is linear: aggregate(x) @ W1 == aggregate(x @ W1).
__global__ void k_scatter_x(const int* __restrict__ edge_index, int E) {
    int e = blockIdx.x * blockDim.x + threadIdx.x;
    if (e >= E) return;
    int s = edge_index[e];
    int d = edge_index[E + e];
    float w = g_deg[s] * g_deg[d];  // dinv[src] * dinv[dst]
    float4 v = reinterpret_cast<const float4*>(g_x4)[s];
    red_add_v4(&g_accx[d * 4], v.x * w, v.y * w, v.z * w, 0.f);
}

// 5) fused: agg1 -> h = relu(agg1 @ W1 + b1) -> t2 = h @ W2 ; seed acc2 with self-loop
__global__ void k_fused_transform(const float* __restrict__ W1, const float* __restrict__ b1,
                                  const float* __restrict__ W2, int n) {
    __shared__ float sW1[96];   // W1 [3, 32] row-major
    __shared__ float sb1[32];
    __shared__ float sW2[96];   // W2 [32, 3] row-major
    if (threadIdx.x < 96) sW1[threadIdx.x] = W1[threadIdx.x];
    if (threadIdx.x < 32) sb1[threadIdx.x] = b1[threadIdx.x];
    if (threadIdx.x >= 128 && threadIdx.x < 224) sW2[threadIdx.x - 128] = W2[threadIdx.x - 128];
    __syncthreads();
    int i = blockIdx.x * blockDim.x + threadIdx.x;
    if (i >= n) return;
    float4 a = reinterpret_cast<const float4*>(g_accx)[i];
    float c0 = 0.f, c1 = 0.f, c2 = 0.f;
#pragma unroll
    for (int j = 0; j < 32; j++) {
        float h = fmaxf(a.x * sW1[j] + a.y * sW1[32 + j] + a.z * sW1[64 + j] + sb1[j], 0.f);
        c0 += h * sW2[j * 3 + 0];
        c1 += h * sW2[j * 3 + 1];
        c2 += h * sW2[j * 3 + 2];
    }
    reinterpret_cast<float4*>(g_t2)[i] = make_float4(c0, c1, c2, 0.f);
    float di = g_deg[i];
    float sl = di * di;
    reinterpret_cast<float4*>(g_acc2)[i] = make_float4(c0 * sl, c1 * sl, c2 * sl, 0.f);
}

// 6) layer-2 scatter: 1 thread per edge, one LDG.128 + one red.v4
__global__ void k_scatter2(const int* __restrict__ edge_index, int E) {
    int e = blockIdx.x * blockDim.x + threadIdx.x;
    if (e >= E) return;
    int s = edge_index[e];
    int d = edge_index[E + e];
    float w = g_deg[s] * g_deg[d];
    float4 t = reinterpret_cast<const float4*>(g_t2)[s];
    red_add_v4(&g_acc2[d * 4], t.x * w, t.y * w, t.z * w, 0.f);
}

// 7) out[i, :] = acc2[i, 0:3] + b2
__global__ void k_out(const float* __restrict__ b2, float* __restrict__ out, int n) {
    int i = blockIdx.x * blockDim.x + threadIdx.x;
    if (i >= n) return;
    float4 a = reinterpret_cast<const float4*>(g_acc2)[i];
    out[i * 3 + 0] = a.x + b2[0];
    out[i * 3 + 1] = a.y + b2[1];
    out[i * 3 + 2] = a.z + b2[2];
}

extern "C" void kernel_launch(void* const* d_in, const int* in_sizes, int n_in,
                              void* d_out, int out_size) {
    const float* x = (const float*)d_in[0];
    const int* edge_index = (const int*)d_in[1];  // int32 (JAX x64 disabled)
    const float* W1 = (const float*)d_in[2];
    const float* b1 = (const float*)d_in[3];
    const float* W2 = (const float*)d_in[4];
    const float* b2 = (const float*)d_in[5];
    float* out = (float*)d_out;

    int n = in_sizes[0] / 3;
    int E = in_sizes[1] / 2;

    const int B = 256;
    k_init_deg<<<(n + B - 1) / B, B>>>(n);
    {
        int t = (E + 3) / 4;
        k_degree4<<<(t + B - 1) / B, B>>>(edge_index, E);
    }
    k_prep<<<(n + B - 1) / B, B>>>(x, n);
    k_scatter_x<<<(E + B - 1) / B, B>>>(edge_index, E);
    k_fused_transform<<<(n + B - 1) / B, B>>>(W1, b1, W2, n);
    k_scatter2<<<(E + B - 1) / B, B>>>(edge_index, E);
    k_out<<<(n + B - 1) / B, B>>>(b2, out, n);
}

// round 10
// speedup vs baseline: 2.4089x; 1.3540x over previous
#include <cuda_runtime.h>
#include <cstdint>

// Problem-fixed maxima (N=100000, E=3200000 per reference setup_inputs).
#define MAXN 100000
#define MAXE 3200000

// Scratch (allocation-free contract: __device__ globals).
__device__ __align__(16) float g_deg[MAXN];        // degree, then overwritten with dinv
__device__ __align__(16) float g_xs[MAXN * 4];     // x * dinv  (source-scaled payload, padded)
__device__ __align__(16) float g_accx[MAXN * 4];   // layer-1 accumulator (pre dst-scale)
__device__ __align__(16) float g_t2s[MAXN * 4];    // t2 * dinv (source-scaled payload, padded)
__device__ __align__(16) float g_acc2[MAXN * 4];   // layer-2 accumulator (pre dst-scale)
__device__ __align__(16) int2  g_edges[MAXE];      // packed (src, dst)

__device__ __forceinline__ void red_add_v4(float* addr, float a, float b, float c, float d) {
    asm volatile("red.global.add.v4.f32 [%0], {%1, %2, %3, %4};"
                 :: "l"(addr), "f"(a), "f"(b), "f"(c), "f"(d) : "memory");
}

__device__ __forceinline__ void red_add_f32(float* addr, float a) {
    asm volatile("red.global.add.f32 [%0], %1;" :: "l"(addr), "f"(a) : "memory");
}

// 1) deg[i] = 1.0 (self-loop)
__global__ void k_init_deg(int n) {
    int i = blockIdx.x * blockDim.x + threadIdx.x;
    if (i < n) g_deg[i] = 1.0f;
}

// 2) in-degree histogram + pack (src,dst) into int2, 4 edges per thread via int4 loads
__global__ void k_degree_pack(const int* __restrict__ edge_index, int E) {
    int i = blockIdx.x * blockDim.x + threadIdx.x;
    int e0 = i * 4;
    if (e0 >= E) return;
    const int* srcp = edge_index;
    const int* dstp = edge_index + E;
    if (e0 + 3 < E) {
        int4 s4 = *reinterpret_cast<const int4*>(srcp + e0);
        int4 d4 = *reinterpret_cast<const int4*>(dstp + e0);
        int4* ep = reinterpret_cast<int4*>(&g_edges[e0]);
        ep[0] = make_int4(s4.x, d4.x, s4.y, d4.y);
        ep[1] = make_int4(s4.z, d4.z, s4.w, d4.w);
        red_add_f32(&g_deg[d4.x], 1.0f);
        red_add_f32(&g_deg[d4.y], 1.0f);
        red_add_f32(&g_deg[d4.z], 1.0f);
        red_add_f32(&g_deg[d4.w], 1.0f);
    } else {
        for (int e = e0; e < E; e++) {
            int s = srcp[e], d = dstp[e];
            g_edges[e] = make_int2(s, d);
            red_add_f32(&g_deg[d], 1.0f);
        }
    }
}

// 3) dinv = rsqrt(deg); payload = x * dinv; seed accumulator with payload (self-loop:
//    post-scale by dinv[d] later yields x[d] * dinv[d]^2).
__global__ void k_prep(const float* __restrict__ x, int n) {
    int i = blockIdx.x * blockDim.x + threadIdx.x;
    if (i >= n) return;
    float di = rsqrtf(g_deg[i]);
    g_deg[i] = di;  // in-place: each thread touches only its own slot
    float x0 = x[i * 3 + 0] * di, x1 = x[i * 3 + 1] * di, x2 = x[i * 3 + 2] * di;
    float4 p = make_float4(x0, x1, x2, 0.f);
    reinterpret_cast<float4*>(g_xs)[i] = p;
    reinterpret_cast<float4*>(g_accx)[i] = p;
}

// 4) layer-1 scatter: weightless copy-scatter. One LDG.64 + one LDG.128 + one RED.128.
__global__ void k_scatter_x(int E) {
    int e = blockIdx.x * blockDim.x + threadIdx.x;
    if (e >= E) return;
    int2 ed = g_edges[e];
    float4 v = reinterpret_cast<const float4*>(g_xs)[ed.x];
    red_add_v4(&g_accx[ed.y * 4], v.x, v.y, v.z, 0.f);
}

// 5) fused: agg1 = accx * dinv (dst post-scale) -> h = relu(agg1 @ W1 + b1) -> t2 = h @ W2;
//    payload t2s = t2 * dinv; seed acc2 with t2s (self-loop).
__global__ void k_fused_transform(const float* __restrict__ W1, const float* __restrict__ b1,
                                  const float* __restrict__ W2, int n) {
    __shared__ float sW1[96];   // W1 [3, 32] row-major
    __shared__ float sb1[32];
    __shared__ float sW2[96];   // W2 [32, 3] row-major
    if (threadIdx.x < 96) sW1[threadIdx.x] = W1[threadIdx.x];
    if (threadIdx.x < 32) sb1[threadIdx.x] = b1[threadIdx.x];
    if (threadIdx.x >= 128 && threadIdx.x < 224) sW2[threadIdx.x - 128] = W2[threadIdx.x - 128];
    __syncthreads();
    int i = blockIdx.x * blockDim.x + threadIdx.x;
    if (i >= n) return;
    float di = g_deg[i];
    float4 a = reinterpret_cast<const float4*>(g_accx)[i];
    a.x *= di; a.y *= di; a.z *= di;  // dst-side normalization of layer-1 aggregation
    float c0 = 0.f, c1 = 0.f, c2 = 0.f;
#pragma unroll
    for (int j = 0; j < 32; j++) {
        float h = fmaxf(a.x * sW1[j] + a.y * sW1[32 + j] + a.z * sW1[64 + j] + sb1[j], 0.f);
        c0 += h * sW2[j * 3 + 0];
        c1 += h * sW2[j * 3 + 1];
        c2 += h * sW2[j * 3 + 2];
    }
    float4 p = make_float4(c0 * di, c1 * di, c2 * di, 0.f);  // source-scaled payload
    reinterpret_cast<float4*>(g_t2s)[i] = p;
    reinterpret_cast<float4*>(g_acc2)[i] = p;                 // self-loop seed
}

// 6) layer-2 scatter: weightless copy-scatter.
__global__ void k_scatter2(int E) {
    int e = blockIdx.x * blockDim.x + threadIdx.x;
    if (e >= E) return;
    int2 ed = g_edges[e];
    float4 v = reinterpret_cast<const float4*>(g_t2s)[ed.x];
    red_add_v4(&g_acc2[ed.y * 4], v.x, v.y, v.z, 0.f);
}

// 7) out[i, :] = acc2[i, 0:3] * dinv[i] + b2 (dst post-scale + bias)
__global__ void k_out(const float* __restrict__ b2, float* __restrict__ out, int n) {
    int i = blockIdx.x * blockDim.x + threadIdx.x;
    if (i >= n) return;
    float di = g_deg[i];
    float4 a = reinterpret_cast<const float4*>(g_acc2)[i];
    out[i * 3 + 0] = a.x * di + b2[0];
    out[i * 3 + 1] = a.y * di + b2[1];
    out[i * 3 + 2] = a.z * di + b2[2];
}

extern "C" void kernel_launch(void* const* d_in, const int* in_sizes, int n_in,
                              void* d_out, int out_size) {
    const float* x = (const float*)d_in[0];
    const int* edge_index = (const int*)d_in[1];  // int32 (JAX x64 disabled)
    const float* W1 = (const float*)d_in[2];
    const float* b1 = (const float*)d_in[3];
    const float* W2 = (const float*)d_in[4];
    const float* b2 = (const float*)d_in[5];
    float* out = (float*)d_out;

    int n = in_sizes[0] / 3;
    int E = in_sizes[1] / 2;

    const int B = 256;
    k_init_deg<<<(n + B - 1) / B, B>>>(n);
    {
        int t = (E + 3) / 4;
        k_degree_pack<<<(t + B - 1) / B, B>>>(edge_index, E);
    }
    k_prep<<<(n + B - 1) / B, B>>>(x, n);
    k_scatter_x<<<(E + B - 1) / B, B>>>(E);
    k_fused_transform<<<(n + B - 1) / B, B>>>(W1, b1, W2, n);
    k_scatter2<<<(E + B - 1) / B, B>>>(E);
    k_out<<<(n + B - 1) / B, B>>>(b2, out, n);
}